// round 4
// baseline (speedup 1.0000x reference)
#include <cuda_runtime.h>
#include <cstdint>

#define P_GAIN     2.0f
#define P_BASELINE 100.0f
static constexpr int B = 32;
static constexpr int E = 64;
static constexpr int H = 128;
static constexpr int W = 128;
static constexpr int R = 13;
static constexpr int D = 32;
static constexpr int HALF = R / 2;
static constexpr int PIX = H * W;           // 16384
static constexpr int BAND = 8;              // rows per band
static constexpr int NBAND = H / BAND;      // 16
static constexpr int BAND_F4 = BAND * W / 4;    // 256 float4 per band
static constexpr int BAND_BYTES = BAND * W * 4; // 4096
static constexpr int PSTRIDE = 176;         // padded 13*13=169

// Scratch: pre-scaled patches and ROI origins (static device globals — no alloc)
__device__ float g_patch[B * E * PSTRIDE];
__device__ int2  g_rc[B * E];

// ---------------------------------------------------------------------------
// Kernel 1: per-emitter tricubic patch evaluation -> g_patch (scaled by
// GAIN * n_photons), plus (r0, c0) -> g_rc.
// ---------------------------------------------------------------------------
__global__ __launch_bounds__(192) void patch_kernel(const float* __restrict__ xyz,
                                                    const float* __restrict__ nph,
                                                    const float* __restrict__ coeff)
{
    const int e = blockIdx.x;            // 0 .. B*E-1
    const int t = threadIdx.x;

    const float x = xyz[e * 3 + 0];
    const float y = xyz[e * 3 + 1];
    const float z = xyz[e * 3 + 2];

    const float xf = floorf(x);
    const float yf = floorf(y);
    const float dx = x - xf;
    const float dy = y - yf;

    float zc = fminf(fmaxf(z, 0.0f), (float)(D - 1) - 1e-6f);
    const float zf = floorf(zc);
    const int   zi = (int)zf;
    const float dz = zc - zf;

    if (t == 0) {
        g_rc[e] = make_int2((int)yf - HALF, (int)xf - HALF);
    }
    if (t >= R * R) return;

    const float px1 = dx, px2 = dx * dx, px3 = px2 * dx;
    const float py1 = dy, py2 = dy * dy, py3 = py2 * dy;
    const float pz1 = dz, pz2 = dz * dz, pz3 = pz2 * dz;
    const float amp = nph[e] * P_GAIN;

    const int r = t / R;
    const int c = t - r * R;
    const float4* __restrict__ base4 =
        reinterpret_cast<const float4*>(coeff + (((size_t)zi * R + r) * R + c) * 64);

    float sum = 0.0f;
    #pragma unroll
    for (int a = 0; a < 4; ++a) {
        const float pza = (a == 0) ? 1.0f : (a == 1) ? pz1 : (a == 2) ? pz2 : pz3;
        float sb = 0.0f;
        #pragma unroll
        for (int b = 0; b < 4; ++b) {
            const float pyb = (b == 0) ? 1.0f : (b == 1) ? py1 : (b == 2) ? py2 : py3;
            const float4 f = base4[a * 4 + b];
            float sc = f.x;
            sc = fmaf(f.y, px1, sc);
            sc = fmaf(f.z, px2, sc);
            sc = fmaf(f.w, px3, sc);
            sb = fmaf(sc, pyb, sb);
        }
        sum = fmaf(sb, pza, sum);
    }
    g_patch[e * PSTRIDE + t] = sum * amp;
}

// ---------------------------------------------------------------------------
// Kernel 2: one block per (frame, band of 8 rows). Loads the scaled bg band
// into smem once. For each emitter of the frame:
//   - no ROI overlap with this band -> cp.async.bulk 4KB smem->gmem (TMA)
//   - overlap -> per-thread float4 STG with patch add (wrap-for-negative,
//     drop-for->=H index semantics, matching JAX .at[].add(mode='drop')).
// ---------------------------------------------------------------------------
__global__ __launch_bounds__(256) void render_kernel(const float* __restrict__ bg,
                                                     float* __restrict__ out)
{
    const int band  = blockIdx.x;        // 0 .. NBAND-1
    const int frame = blockIdx.y;        // 0 .. B-1
    const int bs    = band * BAND;       // first image row of band
    const int t     = threadIdx.x;

    __shared__ float4 s_bg[BAND_F4];     // 4 KB scaled background band
    __shared__ int    s_r0[E];
    __shared__ int    s_c0[E];
    __shared__ int    s_hit[E];

    // ---- load + scale bg band (one float4 per thread) ----
    {
        const float4 b4 = reinterpret_cast<const float4*>(
            bg + (size_t)frame * PIX + (size_t)bs * W)[t];
        float4 v;
        v.x = fmaf(b4.x, P_GAIN, P_BASELINE);
        v.y = fmaf(b4.y, P_GAIN, P_BASELINE);
        v.z = fmaf(b4.z, P_GAIN, P_BASELINE);
        v.w = fmaf(b4.w, P_GAIN, P_BASELINE);
        s_bg[t] = v;
    }

    // ---- per-emitter band-intersection flags ----
    if (t < E) {
        const int2 rc = g_rc[frame * E + t];
        s_r0[t] = rc.x;
        s_c0[t] = rc.y;
        int hit = 0;
        #pragma unroll
        for (int lr = 0; lr < BAND; ++lr) {
            int rr = bs + lr - rc.x;     // in [-121, 133]
            if (rr >= H) rr -= H;        // wrapped negative target row
            if ((unsigned)rr < (unsigned)R) hit = 1;
        }
        s_hit[t] = hit;
    }
    __syncthreads();

    // ---- non-hit emitters: bulk smem->gmem copies (issued by thread 0) ----
    if (t == 0) {
        asm volatile("fence.proxy.async.shared::cta;" ::: "memory");
        uint32_t src;
        asm("{ .reg .u64 tmp; cvta.to.shared.u64 tmp, %1; cvt.u32.u64 %0, tmp; }"
            : "=r"(src) : "l"(s_bg));
        #pragma unroll 1
        for (int e2 = 0; e2 < E; ++e2) {
            if (!s_hit[e2]) {
                float* dst = out + ((size_t)(frame * E + e2) * PIX) + (size_t)bs * W;
                asm volatile(
                    "cp.async.bulk.global.shared::cta.bulk_group [%0], [%1], %2;"
                    :: "l"(dst), "r"(src), "r"((unsigned)BAND_BYTES) : "memory");
            }
        }
        asm volatile("cp.async.bulk.commit_group;" ::: "memory");
    }

    // ---- hit emitters: per-thread STG with patch add ----
    const float4 base_v = s_bg[t];
    const int pix = t * 4;
    const int lr  = pix >> 7;            // local row (W == 128)
    const int col = pix & (W - 1);
    const int row = bs + lr;

    #pragma unroll 1
    for (int e2 = 0; e2 < E; ++e2) {
        if (!s_hit[e2]) continue;
        const int r0 = s_r0[e2];
        const int c0 = s_c0[e2];
        float4 v = base_v;

        int rr = row - r0;
        if (rr >= H) rr -= H;            // wrapped negative target row
        if ((unsigned)rr < (unsigned)R) {
            const float* __restrict__ pp =
                g_patch + (size_t)(frame * E + e2) * PSTRIDE + rr * R;
            float* vp = &v.x;
            #pragma unroll
            for (int j = 0; j < 4; ++j) {
                int cj = col - c0 + j;
                if (cj >= W) cj -= W;    // wrapped negative target col
                if ((unsigned)cj < (unsigned)R) vp[j] += pp[cj];
            }
        }
        reinterpret_cast<float4*>(
            out + (size_t)(frame * E + e2) * PIX + (size_t)bs * W)[t] = v;
    }

    // ---- drain bulk stores before smem is released ----
    if (t == 0) {
        asm volatile("cp.async.bulk.wait_group 0;" ::: "memory");
    }
}

// ---------------------------------------------------------------------------
// Launch. Inputs identified by element count:
//   xyz [B,E,3]=6144, n_photons [B,E]=2048, bg [B,H,W]=524288,
//   coeff [D,R,R,4,4,4]=346112.  Output: [B,E,H,W] f32.
// ---------------------------------------------------------------------------
extern "C" void kernel_launch(void* const* d_in, const int* in_sizes, int n_in,
                              void* d_out, int out_size)
{
    const float* xyz   = nullptr;
    const float* nph   = nullptr;
    const float* bg    = nullptr;
    const float* coeff = nullptr;
    for (int i = 0; i < n_in; ++i) {
        switch (in_sizes[i]) {
            case B * E * 3:      xyz   = (const float*)d_in[i]; break;
            case B * E:          nph   = (const float*)d_in[i]; break;
            case B * H * W:      bg    = (const float*)d_in[i]; break;
            case D * R * R * 64: coeff = (const float*)d_in[i]; break;
        }
    }
    float* out = (float*)d_out;

    patch_kernel<<<B * E, 192>>>(xyz, nph, coeff);
    dim3 grid(NBAND, B);
    render_kernel<<<grid, 256>>>(bg, out);
}

// round 5
// speedup vs baseline: 1.0234x; 1.0234x over previous
#include <cuda_runtime.h>
#include <cstdint>

#define P_GAIN     2.0f
#define P_BASELINE 100.0f
static constexpr int B = 32;
static constexpr int E = 64;
static constexpr int H = 128;
static constexpr int W = 128;
static constexpr int R = 13;
static constexpr int D = 32;
static constexpr int HALF = R / 2;
static constexpr int PIX = H * W;               // 16384
static constexpr int BAND = 8;                  // rows per band
static constexpr int NBAND = H / BAND;          // 16
static constexpr int BAND_F4 = BAND * W / 4;    // 256 float4 per band
static constexpr int BAND_BYTES = BAND * W * 4; // 4096
static constexpr int PB_W = 16;                 // padded patch row (13 -> 16)

// ---------------------------------------------------------------------------
// Fully fused kernel: one block per (frame, 8-row band).
//  1. Load + scale the bg band into smem (once per band, not per emitter).
//  2. Threads 0..63 classify each emitter: does its 13x13 ROI touch this band
//     (with JAX negative-index WRAP semantics)? Build compacted hit list.
//  3. All 256 threads cooperatively evaluate the tricubic spline for the
//     needed (hit emitter, band row, patch col) pixels into smem.
//  4. Miss emitters: thread 0 issues cp.async.bulk 4KB smem->gmem (TMA path,
//     zero per-thread store issue). Hit emitters: per-thread float4 STG with
//     the patch added from smem.
// Index semantics: negative scatter targets wrap (+H / +W); >= H/W dropped.
// ---------------------------------------------------------------------------
__global__ __launch_bounds__(256) void fused_kernel(const float* __restrict__ xyz,
                                                    const float* __restrict__ nph,
                                                    const float* __restrict__ bg,
                                                    const float* __restrict__ coeff,
                                                    float* __restrict__ out)
{
    const int band  = blockIdx.x;        // 0 .. NBAND-1
    const int frame = blockIdx.y;        // 0 .. B-1
    const int bs    = band * BAND;       // first image row of band
    const int t     = threadIdx.x;

    __shared__ float4 s_bg[BAND_F4];     // 4 KB scaled background band
    __shared__ float  s_pb[E][BAND][PB_W]; // 32 KB patch rows for this band
    __shared__ int    s_r0[E];
    __shared__ int    s_c0[E];
    __shared__ unsigned char s_hit[E];
    __shared__ int    s_list[E];
    __shared__ int    s_nhit;

    if (t == 0) s_nhit = 0;

    // ---- load + scale bg band ----
    {
        const float4 b4 = reinterpret_cast<const float4*>(
            bg + (size_t)frame * PIX + (size_t)bs * W)[t];
        float4 v;
        v.x = fmaf(b4.x, P_GAIN, P_BASELINE);
        v.y = fmaf(b4.y, P_GAIN, P_BASELINE);
        v.z = fmaf(b4.z, P_GAIN, P_BASELINE);
        v.w = fmaf(b4.w, P_GAIN, P_BASELINE);
        s_bg[t] = v;
    }
    __syncthreads();   // s_nhit=0 visible before atomics

    // ---- classify emitters ----
    if (t < E) {
        const int ge = frame * E + t;
        const float x = xyz[ge * 3 + 0];
        const float y = xyz[ge * 3 + 1];
        const int r0 = (int)floorf(y) - HALF;
        const int c0 = (int)floorf(x) - HALF;
        s_r0[t] = r0;
        s_c0[t] = c0;
        int hit = 0;
        #pragma unroll
        for (int lr = 0; lr < BAND; ++lr) {
            int rr = bs + lr - r0;       // in [-121, 133]
            if (rr >= H) rr -= H;        // wrapped negative target row
            if ((unsigned)rr < (unsigned)R) hit = 1;
        }
        s_hit[t] = (unsigned char)hit;
        if (hit) {
            const int idx = atomicAdd(&s_nhit, 1);
            s_list[idx] = t;
        }
    }
    __syncthreads();

    // ---- cooperative patch evaluation for hit emitters ----
    const int nhit = s_nhit;
    const int work = nhit * (BAND * R);
    for (int i = t; i < work; i += 256) {
        const int h  = i / (BAND * R);
        const int p  = i - h * (BAND * R);
        const int lr = p / R;
        const int cx = p - lr * R;
        const int em = s_list[h];

        int rr = bs + lr - s_r0[em];
        if (rr >= H) rr -= H;
        if ((unsigned)rr >= (unsigned)R) continue;   // band row unused

        const int ge = frame * E + em;
        const float x = xyz[ge * 3 + 0];
        const float y = xyz[ge * 3 + 1];
        const float z = xyz[ge * 3 + 2];
        const float dx = x - floorf(x);
        const float dy = y - floorf(y);
        float zc = fminf(fmaxf(z, 0.0f), (float)(D - 1) - 1e-6f);
        const float zf = floorf(zc);
        const int   zi = (int)zf;
        const float dz = zc - zf;

        const float px1 = dx, px2 = dx * dx, px3 = px2 * dx;
        const float py1 = dy, py2 = dy * dy, py3 = py2 * dy;
        const float pz1 = dz, pz2 = dz * dz, pz3 = pz2 * dz;
        const float amp = nph[ge] * P_GAIN;

        const float4* __restrict__ base4 =
            reinterpret_cast<const float4*>(coeff + (((size_t)zi * R + rr) * R + cx) * 64);

        float sum = 0.0f;
        #pragma unroll
        for (int a = 0; a < 4; ++a) {
            const float pza = (a == 0) ? 1.0f : (a == 1) ? pz1 : (a == 2) ? pz2 : pz3;
            float sb = 0.0f;
            #pragma unroll
            for (int b = 0; b < 4; ++b) {
                const float pyb = (b == 0) ? 1.0f : (b == 1) ? py1 : (b == 2) ? py2 : py3;
                const float4 f = base4[a * 4 + b];
                float sc = f.x;
                sc = fmaf(f.y, px1, sc);
                sc = fmaf(f.z, px2, sc);
                sc = fmaf(f.w, px3, sc);
                sb = fmaf(sc, pyb, sb);
            }
            sum = fmaf(sb, pza, sum);
        }
        s_pb[em][lr][cx] = sum * amp;
    }
    __syncthreads();

    // ---- miss emitters: TMA bulk smem->gmem band copies ----
    if (t == 0) {
        asm volatile("fence.proxy.async.shared::cta;" ::: "memory");
        uint32_t src;
        asm("{ .reg .u64 tmp; cvta.to.shared.u64 tmp, %1; cvt.u32.u64 %0, tmp; }"
            : "=r"(src) : "l"(s_bg));
        #pragma unroll 1
        for (int e2 = 0; e2 < E; ++e2) {
            if (!s_hit[e2]) {
                float* dst = out + (size_t)(frame * E + e2) * PIX + (size_t)bs * W;
                asm volatile(
                    "cp.async.bulk.global.shared::cta.bulk_group [%0], [%1], %2;"
                    :: "l"(dst), "r"(src), "r"((unsigned)BAND_BYTES) : "memory");
            }
        }
        asm volatile("cp.async.bulk.commit_group;" ::: "memory");
    }

    // ---- hit emitters: per-thread float4 STG with patch add ----
    const float4 base_v = s_bg[t];
    const int pix = t * 4;
    const int lr  = pix >> 7;            // local row (W == 128)
    const int col = pix & (W - 1);

    #pragma unroll 1
    for (int k = 0; k < nhit; ++k) {
        const int em = s_list[k];
        const int r0 = s_r0[em];
        const int c0 = s_c0[em];
        float4 v = base_v;

        int rr = bs + lr - r0;
        if (rr >= H) rr -= H;            // wrapped negative target row
        if ((unsigned)rr < (unsigned)R) {
            const float* __restrict__ pp = &s_pb[em][lr][0];
            float* vp = &v.x;
            #pragma unroll
            for (int j = 0; j < 4; ++j) {
                int cj = col - c0 + j;
                if (cj >= W) cj -= W;    // wrapped negative target col
                if ((unsigned)cj < (unsigned)R) vp[j] += pp[cj];
            }
        }
        reinterpret_cast<float4*>(
            out + (size_t)(frame * E + em) * PIX + (size_t)bs * W)[t] = v;
    }

    // ---- drain bulk stores before smem is released ----
    if (t == 0) {
        asm volatile("cp.async.bulk.wait_group 0;" ::: "memory");
    }
}

// ---------------------------------------------------------------------------
// Launch. Inputs identified by element count:
//   xyz [B,E,3]=6144, n_photons [B,E]=2048, bg [B,H,W]=524288,
//   coeff [D,R,R,4,4,4]=346112.  Output: [B,E,H,W] f32.
// ---------------------------------------------------------------------------
extern "C" void kernel_launch(void* const* d_in, const int* in_sizes, int n_in,
                              void* d_out, int out_size)
{
    const float* xyz   = nullptr;
    const float* nph   = nullptr;
    const float* bg    = nullptr;
    const float* coeff = nullptr;
    for (int i = 0; i < n_in; ++i) {
        switch (in_sizes[i]) {
            case B * E * 3:      xyz   = (const float*)d_in[i]; break;
            case B * E:          nph   = (const float*)d_in[i]; break;
            case B * H * W:      bg    = (const float*)d_in[i]; break;
            case D * R * R * 64: coeff = (const float*)d_in[i]; break;
        }
    }
    float* out = (float*)d_out;

    dim3 grid(NBAND, B);
    fused_kernel<<<grid, 256>>>(xyz, nph, bg, coeff, out);
}

// round 6
// speedup vs baseline: 1.2723x; 1.2433x over previous
#include <cuda_runtime.h>
#include <cstdint>

#define P_GAIN     2.0f
#define P_BASELINE 100.0f
static constexpr int B = 32;
static constexpr int E = 64;
static constexpr int H = 128;
static constexpr int W = 128;
static constexpr int R = 13;
static constexpr int D = 32;
static constexpr int HALF = R / 2;
static constexpr int PIX = H * W;               // 16384
static constexpr int BAND = 4;                  // rows per band
static constexpr int NBAND = H / BAND;          // 32
static constexpr int BAND_F4 = BAND * W / 4;    // 128 float4 per band
static constexpr int BAND_BYTES = BAND * W * 4; // 2048
static constexpr int PPAD = 176;                // padded 13*13=169

// Transposed coeff table: g_cT[z][k][pixel], pixel = r*13+c contiguous.
// Makes the per-pixel spline dot fully coalesced across lanes.
__device__ float g_cT[D * 64 * PPAD];           // 1.44 MB, L2-resident

// ---------------------------------------------------------------------------
// Prep: transpose coeff [D][R][R][64] -> g_cT [D][64][169pad]
// ---------------------------------------------------------------------------
__global__ __launch_bounds__(192) void prep_kernel(const float* __restrict__ coeff)
{
    const int z = blockIdx.x;   // 0..D-1
    const int k = blockIdx.y;   // 0..63
    const int t = threadIdx.x;
    if (t < R * R) {
        g_cT[((size_t)z * 64 + k) * PPAD + t] =
            coeff[((size_t)z * R * R + t) * 64 + k];
    }
}

// ---------------------------------------------------------------------------
// Fused render: one block per (frame, 4-row band), 128 threads.
//  1. load+scale bg band into smem (once)
//  2. classify 64 emitters vs band (JAX wrap-negative / drop->=H semantics),
//     precompute per-emitter weights pz[a]*py[b] (16) and px[c] (4)
//  3. cooperative COALESCED spline eval of needed patch rows via g_cT
//  4. miss emitters -> cp.async.bulk 2KB smem->gmem; hit emitters ->
//     per-thread float4 STG with patch add
// ---------------------------------------------------------------------------
__global__ __launch_bounds__(128) void fused_kernel(const float* __restrict__ xyz,
                                                    const float* __restrict__ nph,
                                                    const float* __restrict__ bg,
                                                    float* __restrict__ out)
{
    const int band  = blockIdx.x;        // 0 .. NBAND-1
    const int frame = blockIdx.y;        // 0 .. B-1
    const int bs    = band * BAND;
    const int t     = threadIdx.x;

    __shared__ float4 s_bg[BAND_F4];         // 2 KB scaled bg band
    __shared__ float  s_pb[E][BAND][16];     // 16 KB patch rows (this band)
    __shared__ float  s_wzy[E][16];          // pz[a]*py[b]
    __shared__ float  s_px[E][4];            // px[c]
    __shared__ float  s_amp[E];
    __shared__ int    s_r0[E];
    __shared__ int    s_c0[E];
    __shared__ int    s_zi[E];
    __shared__ unsigned char s_hit[E];
    __shared__ int    s_list[E];
    __shared__ int    s_nhit;

    if (t == 0) s_nhit = 0;

    // ---- load + scale bg band ----
    {
        const float4 b4 = reinterpret_cast<const float4*>(
            bg + (size_t)frame * PIX + (size_t)bs * W)[t];
        float4 v;
        v.x = fmaf(b4.x, P_GAIN, P_BASELINE);
        v.y = fmaf(b4.y, P_GAIN, P_BASELINE);
        v.z = fmaf(b4.z, P_GAIN, P_BASELINE);
        v.w = fmaf(b4.w, P_GAIN, P_BASELINE);
        s_bg[t] = v;
    }
    __syncthreads();

    // ---- classify emitters + per-emitter weight precompute ----
    if (t < E) {
        const int ge = frame * E + t;
        const float x = xyz[ge * 3 + 0];
        const float y = xyz[ge * 3 + 1];
        const float z = xyz[ge * 3 + 2];
        const float xf = floorf(x);
        const float yf = floorf(y);
        const float dx = x - xf;
        const float dy = y - yf;
        float zc = fminf(fmaxf(z, 0.0f), (float)(D - 1) - 1e-6f);
        const float zf = floorf(zc);
        const float dz = zc - zf;

        const int r0 = (int)yf - HALF;
        s_r0[t] = r0;
        s_c0[t] = (int)xf - HALF;
        s_zi[t] = (int)zf;
        s_amp[t] = nph[ge] * P_GAIN;

        float px[4], py[4], pz[4];
        px[0] = 1.0f; px[1] = dx; px[2] = dx * dx; px[3] = px[2] * dx;
        py[0] = 1.0f; py[1] = dy; py[2] = dy * dy; py[3] = py[2] * dy;
        pz[0] = 1.0f; pz[1] = dz; pz[2] = dz * dz; pz[3] = pz[2] * dz;
        #pragma unroll
        for (int c = 0; c < 4; ++c) s_px[t][c] = px[c];
        #pragma unroll
        for (int a = 0; a < 4; ++a)
            #pragma unroll
            for (int b = 0; b < 4; ++b)
                s_wzy[t][a * 4 + b] = pz[a] * py[b];

        int hit = 0;
        #pragma unroll
        for (int lr = 0; lr < BAND; ++lr) {
            int rr = bs + lr - r0;       // negative targets wrap (+H)
            if (rr >= H) rr -= H;
            if ((unsigned)rr < (unsigned)R) hit = 1;
        }
        s_hit[t] = (unsigned char)hit;
        if (hit) s_list[atomicAdd(&s_nhit, 1)] = t;
    }
    __syncthreads();

    // ---- cooperative coalesced patch eval ----
    const int nhit = s_nhit;
    const int work = nhit * (BAND * R);       // tasks: (hit, band row, col)
    const float* __restrict__ cT = g_cT;
    for (int i = t; i < work; i += 128) {
        const int h  = i / (BAND * R);
        const int p  = i - h * (BAND * R);
        const int lr = p / R;
        const int cx = p - lr * R;
        const int em = s_list[h];

        int rr = bs + lr - s_r0[em];
        if (rr >= H) rr -= H;
        if ((unsigned)rr >= (unsigned)R) continue;

        const float* __restrict__ base = cT + (size_t)s_zi[em] * 64 * PPAD
                                            + rr * R + cx;
        const float* __restrict__ wz = s_wzy[em];
        const float* __restrict__ pxv = s_px[em];

        float sum = 0.0f;
        #pragma unroll 8
        for (int k = 0; k < 64; ++k) {
            const float w = wz[k >> 2] * pxv[k & 3];
            sum = fmaf(base[k * PPAD], w, sum);
        }
        s_pb[em][lr][cx] = sum * s_amp[em];
    }
    __syncthreads();

    // ---- miss emitters: bulk smem->gmem band copies (TMA path) ----
    if (t == 0) {
        asm volatile("fence.proxy.async.shared::cta;" ::: "memory");
        uint32_t src;
        asm("{ .reg .u64 tmp; cvta.to.shared.u64 tmp, %1; cvt.u32.u64 %0, tmp; }"
            : "=r"(src) : "l"(s_bg));
        #pragma unroll 1
        for (int e2 = 0; e2 < E; ++e2) {
            if (!s_hit[e2]) {
                float* dst = out + (size_t)(frame * E + e2) * PIX + (size_t)bs * W;
                asm volatile(
                    "cp.async.bulk.global.shared::cta.bulk_group [%0], [%1], %2;"
                    :: "l"(dst), "r"(src), "r"((unsigned)BAND_BYTES) : "memory");
            }
        }
        asm volatile("cp.async.bulk.commit_group;" ::: "memory");
    }

    // ---- hit emitters: per-thread float4 STG with patch add ----
    const float4 base_v = s_bg[t];
    const int pix = t * 4;
    const int lr  = pix >> 7;            // local row (W == 128)
    const int col = pix & (W - 1);

    #pragma unroll 1
    for (int kk = 0; kk < nhit; ++kk) {
        const int em = s_list[kk];
        const int r0 = s_r0[em];
        const int c0 = s_c0[em];
        float4 v = base_v;

        int rr = bs + lr - r0;
        if (rr >= H) rr -= H;            // wrapped negative target row
        if ((unsigned)rr < (unsigned)R) {
            const float* __restrict__ pp = &s_pb[em][lr][0];
            float* vp = &v.x;
            #pragma unroll
            for (int j = 0; j < 4; ++j) {
                int cj = col - c0 + j;
                if (cj >= W) cj -= W;    // wrapped negative target col
                if ((unsigned)cj < (unsigned)R) vp[j] += pp[cj];
            }
        }
        reinterpret_cast<float4*>(
            out + (size_t)(frame * E + em) * PIX + (size_t)bs * W)[t] = v;
    }

    // ---- drain bulk stores before smem is released ----
    if (t == 0) {
        asm volatile("cp.async.bulk.wait_group 0;" ::: "memory");
    }
}

// ---------------------------------------------------------------------------
// Launch. Inputs identified by element count:
//   xyz [B,E,3]=6144, n_photons [B,E]=2048, bg [B,H,W]=524288,
//   coeff [D,R,R,4,4,4]=346112.  Output: [B,E,H,W] f32.
// ---------------------------------------------------------------------------
extern "C" void kernel_launch(void* const* d_in, const int* in_sizes, int n_in,
                              void* d_out, int out_size)
{
    const float* xyz   = nullptr;
    const float* nph   = nullptr;
    const float* bg    = nullptr;
    const float* coeff = nullptr;
    for (int i = 0; i < n_in; ++i) {
        switch (in_sizes[i]) {
            case B * E * 3:      xyz   = (const float*)d_in[i]; break;
            case B * E:          nph   = (const float*)d_in[i]; break;
            case B * H * W:      bg    = (const float*)d_in[i]; break;
            case D * R * R * 64: coeff = (const float*)d_in[i]; break;
        }
    }
    float* out = (float*)d_out;

    dim3 pgrid(D, 64);
    prep_kernel<<<pgrid, 192>>>(coeff);
    dim3 grid(NBAND, B);
    fused_kernel<<<grid, 128>>>(xyz, nph, bg, out);
}